// round 12
// baseline (speedup 1.0000x reference)
#include <cuda_runtime.h>
#include <cuda_bf16.h>

// Problem constants (fixed by setup_inputs)
#define Bn 4
#define Cn 32
#define Hn 128
#define Wn 128
#define Kn 128
#define Vn 16          // Cn/2 vertices per polygon
#define HWn (Hn * Wn)
#define BKn (Bn * Kn)  // 512

// Single packed accumulator (zero-init; reset by last block each replay)
//   bits [ 0:40) : sum(iou*mask) in 10.30 fixed point  (max 512 * 2^30 < 2^39)
//   bits [40:50) : sum(mask)                           (max 512)
//   bits [50:60) : completion count                    (max 512)
__device__ unsigned long long g_acc;

typedef unsigned long long ull;

// ~0ull >> n with PTX clamp semantics: n >= 64 -> 0
__device__ __forceinline__ ull shr64c(int n) {
    ull r;
    asm("shr.u64 %0, %1, %2;" : "=l"(r) : "l"(~0ULL), "r"(n));
    return r;
}

__global__ void __launch_bounds__(128)
iou_fused_kernel(const float* __restrict__ out4d,   // [B,C,H,W]
                 const int*   __restrict__ mask,    // [B,K]
                 const int*   __restrict__ ind,     // [B,K]
                 const float* __restrict__ target,  // [B,C,K]
                 float*       __restrict__ loss)    // [1]
{
    const int bk  = blockIdx.x;
    const int b   = bk >> 7;            // / Kn
    const int k   = bk & (Kn - 1);
    const int tid = threadIdx.x;        // 0..127 == scanline row

    // One float4 per edge: (y1, slope, x1, bitcast(ymin | range<<16))
    __shared__ float4 edge[2][Vn];

    // ---- warp 0: load vertices, exchange via shfl, build edge params ----
    if (tid < 32) {
        const int pv = tid >> 4;        // 0 = pred, 1 = gt
        const int v  = tid & 15;
        float x, y;
        if (pv == 0) {
            const int idx = ind[bk];
            x = out4d[(size_t)(b * Cn + 2 * v)     * HWn + idx];
            y = out4d[(size_t)(b * Cn + 2 * v + 1) * HWn + idx];
        } else {
            x = target[(size_t)(b * Cn + 2 * v)     * Kn + k];
            y = target[(size_t)(b * Cn + 2 * v + 1) * Kn + k];
        }
        const float x1 = truncf(x) + 100.0f;
        const float y1 = truncf(y) + 100.0f;
        const int nxt = (pv << 4) | ((v + 1) & 15);
        const float x2 = __shfl_sync(0xFFFFFFFFu, x1, nxt);
        const float y2 = __shfl_sync(0xFFFFFFFFu, y1, nxt);
        const float d  = y2 - y1;
        const float s  = __fdividef(x2 - x1, d);   // inf/NaN when d==0: never crossed
        const int iymin = (int)fminf(y1, y2);
        const int iymax = (int)fmaxf(y1, y2);
        const int pk = iymin | ((iymax - iymin) << 16);
        edge[pv][v] = make_float4(y1, s, x1, __int_as_float(pk));
    }
    __syncthreads();

    // ---- rasterize BOTH polygons at my row: XOR of prefix masks per edge ----
    const float py = (float)tid;
    ull plo = 0, phi = 0, glo = 0, ghi = 0;
#pragma unroll
    for (int v = 0; v < Vn; v++) {
        const float4 e = edge[0][v];
        const int pk = __float_as_int(e.w);
        const bool crosses = (unsigned)(tid - (pk & 0xFFFF)) < (unsigned)(pk >> 16);
        const float xint = fmaf(py - e.x, e.y, e.z);
        const int m = crosses ? __float2int_ru(xint) : 0;   // m in [10,121] when crossing
        plo ^= shr64c(64  - min(m, 64));
        phi ^= shr64c(128 - max(m, 64));
    }
#pragma unroll
    for (int v = 0; v < Vn; v++) {
        const float4 e = edge[1][v];
        const int pk = __float_as_int(e.w);
        const bool crosses = (unsigned)(tid - (pk & 0xFFFF)) < (unsigned)(pk >> 16);
        const float xint = fmaf(py - e.x, e.y, e.z);
        const int m = crosses ? __float2int_ru(xint) : 0;
        glo ^= shr64c(64  - min(m, 64));
        ghi ^= shr64c(128 - max(m, 64));
    }

    // per-thread contributions (no smem exchange needed)
    int my_inter = __popcll(plo & glo) + __popcll(phi & ghi);
    int my_pg    = __popcll(plo) + __popcll(phi)
                 + __popcll(glo) + __popcll(ghi);           // parea + garea

    // ---- block reduce (128 threads = 4 warps) ----
    __shared__ int s_i[4], s_a[4];
#pragma unroll
    for (int off = 16; off > 0; off >>= 1) {
        my_inter += __shfl_down_sync(0xFFFFFFFFu, my_inter, off);
        my_pg    += __shfl_down_sync(0xFFFFFFFFu, my_pg,    off);
    }
    if ((tid & 31) == 0) { s_i[tid >> 5] = my_inter; s_a[tid >> 5] = my_pg; }
    __syncthreads();

    if (tid == 0) {
        const int I  = s_i[0] + s_i[1] + s_i[2] + s_i[3];
        const int PG = s_a[0] + s_a[1] + s_a[2] + s_a[3];
        const float interf = (float)I;
        const float unionf = (float)PG - interf;
        const float iou = interf / (unionf + 0.0001f);
        const int   m   = mask[bk];
        // 10.30 fixed point, deterministic conversion; pack with den and count
        const ull fx = (ull)((double)(iou * (float)m) * 1073741824.0);  // 2^30
        const ull my = fx | ((ull)(unsigned)m << 40) | (1ull << 50);
        const ull old = atomicAdd(&g_acc, my);
        if ((old >> 50) == (ull)(BKn - 1)) {
            const ull tot = old + my;               // totals incl. my contribution
            const float N = (float)((double)(tot & ((1ull << 40) - 1)) * (1.0 / 1073741824.0));
            const float D = (float)((unsigned)(tot >> 40) & 0x3FFu);
            loss[0] = 1.0f - N / (D + 0.0001f);
            g_acc = 0ull;   // all 512 writers done; safe reset for next replay
        }
    }
}

extern "C" void kernel_launch(void* const* d_in, const int* in_sizes, int n_in,
                              void* d_out, int out_size) {
    const float* out4d  = (const float*)d_in[0];   // output  [B,C,H,W]
    const int*   mask   = (const int*)  d_in[1];   // mask    [B,K]
    const int*   ind    = (const int*)  d_in[2];   // ind     [B,K]
    const float* target = (const float*)d_in[3];   // target  [B,C,K]
    float* loss = (float*)d_out;

    iou_fused_kernel<<<BKn, 128>>>(out4d, mask, ind, target, loss);
}

// round 14
// speedup vs baseline: 1.0294x; 1.0294x over previous
#include <cuda_runtime.h>
#include <cuda_bf16.h>

// Problem constants (fixed by setup_inputs)
#define Bn 4
#define Cn 32
#define Hn 128
#define Wn 128
#define Kn 128
#define Vn 16          // Cn/2 vertices per polygon
#define HWn (Hn * Wn)
#define BKn (Bn * Kn)  // 512

// Single packed accumulator (zero-init; reset by last block each replay)
//   bits [ 0:40) : sum(iou*mask) in 10.30 fixed point  (max 512 * 2^30 < 2^39)
//   bits [40:50) : sum(mask)                           (max 512)
//   bits [50:60) : completion count                    (max 512)
__device__ unsigned long long g_acc;

typedef unsigned long long ull;

// ~0ull >> n with PTX clamp semantics: n >= 64 (or <0 as unsigned) -> 0
__device__ __forceinline__ ull shr64c(int n) {
    ull r;
    asm("shr.u64 %0, %1, %2;" : "=l"(r) : "l"(~0ULL), "r"(n));
    return r;
}

__global__ void __launch_bounds__(128)
iou_fused_kernel(const float* __restrict__ out4d,   // [B,C,H,W]
                 const int*   __restrict__ mask,    // [B,K]
                 const int*   __restrict__ ind,     // [B,K]
                 const float* __restrict__ target,  // [B,C,K]
                 float*       __restrict__ loss)    // [1]
{
    const int bk   = blockIdx.x;
    const int b    = bk >> 7;           // / Kn
    const int k    = bk & (Kn - 1);
    const int tid  = threadIdx.x;       // 0..127 == scanline row
    const int wid  = tid >> 5;
    const int lane = tid & 31;

    // Per-warp private edge tables: slot j<16 = pred edge j, j>=16 = gt edge j-16.
    // float4 = (y1, slope, x1, bitcast(ymin | range<<16))
    __shared__ float4 edge_w[4][32];
    __shared__ unsigned int s_part[4];

    // ---- EVERY warp builds its own edge table (no cross-warp dependency) ----
    {
        const int pv = lane >> 4;       // 0 = pred, 1 = gt
        const int v  = lane & 15;
        float x, y;
        if (pv == 0) {
            const int idx = ind[bk];
            x = out4d[(size_t)(b * Cn + 2 * v)     * HWn + idx];
            y = out4d[(size_t)(b * Cn + 2 * v + 1) * HWn + idx];
        } else {
            x = target[(size_t)(b * Cn + 2 * v)     * Kn + k];
            y = target[(size_t)(b * Cn + 2 * v + 1) * Kn + k];
        }
        const float x1 = truncf(x) + 100.0f;
        const float y1 = truncf(y) + 100.0f;
        const int nxt = (pv << 4) | ((v + 1) & 15);
        const float x2 = __shfl_sync(0xFFFFFFFFu, x1, nxt);
        const float y2 = __shfl_sync(0xFFFFFFFFu, y1, nxt);
        const float d  = y2 - y1;
        const float s  = __fdividef(x2 - x1, d);   // inf/NaN when d==0: never crossed
        const int iymin = (int)fminf(y1, y2);
        const int iymax = (int)fmaxf(y1, y2);
        const int pk = iymin | ((iymax - iymin) << 16);
        edge_w[wid][lane] = make_float4(y1, s, x1, __int_as_float(pk));
        __syncwarp();
    }

    // ---- rasterize BOTH polygons at my row from MY warp's table ----
    const float py = (float)tid;
    ull plo = 0, phi = 0, glo = 0, ghi = 0;
#pragma unroll
    for (int v = 0; v < Vn; v++) {
        const float4 e = edge_w[wid][v];              // pred edge v (broadcast LDS)
        const int pk = __float_as_int(e.w);
        const bool crosses = (unsigned)(tid - (pk & 0xFFFF)) < (unsigned)(pk >> 16);
        const float xint = fmaf(py - e.x, e.y, e.z);
        const int m = crosses ? __float2int_ru(xint) : 0;   // m in [10,121] when crossing
        plo ^= shr64c(64 - min(m, 64));               // low min(m,64) bits
        phi ^= shr64c(128 - m);                       // bits [64,m); self-clamps for m<64
    }
#pragma unroll
    for (int v = 0; v < Vn; v++) {
        const float4 e = edge_w[wid][16 + v];         // gt edge v
        const int pk = __float_as_int(e.w);
        const bool crosses = (unsigned)(tid - (pk & 0xFFFF)) < (unsigned)(pk >> 16);
        const float xint = fmaf(py - e.x, e.y, e.z);
        const int m = crosses ? __float2int_ru(xint) : 0;
        glo ^= shr64c(64 - min(m, 64));
        ghi ^= shr64c(128 - m);
    }

    // per-thread contribution, packed: inter in [0:16), parea+garea in [16:32)
    const int inter = __popcll(plo & glo) + __popcll(phi & ghi);
    const int pg    = __popcll(plo) + __popcll(phi)
                    + __popcll(glo) + __popcll(ghi);
    // block maxima: inter<=16384, pg<=32768 -> both fields safe from overflow
    unsigned int contrib = (unsigned int)inter | ((unsigned int)pg << 16);

    // ---- warp reduce in ONE instruction, then tiny cross-warp combine ----
    const unsigned int wsum = __reduce_add_sync(0xFFFFFFFFu, contrib);
    if (lane == 0) s_part[wid] = wsum;
    __syncthreads();

    if (tid == 0) {
        const unsigned int t = s_part[0] + s_part[1] + s_part[2] + s_part[3];
        const int I  = (int)(t & 0xFFFFu);
        const int PG = (int)(t >> 16);
        const float interf = (float)I;
        const float unionf = (float)PG - interf;
        const float iou = interf / (unionf + 0.0001f);
        const int   m   = mask[bk];
        // 10.30 fixed point, deterministic conversion; pack with den and count
        const ull fx = (ull)((double)(iou * (float)m) * 1073741824.0);  // 2^30
        const ull my = fx | ((ull)(unsigned)m << 40) | (1ull << 50);
        const ull old = atomicAdd(&g_acc, my);
        if ((old >> 50) == (ull)(BKn - 1)) {
            const ull tot = old + my;               // totals incl. my contribution
            const float N = (float)((double)(tot & ((1ull << 40) - 1)) * (1.0 / 1073741824.0));
            const float D = (float)((unsigned)(tot >> 40) & 0x3FFu);
            loss[0] = 1.0f - N / (D + 0.0001f);
            g_acc = 0ull;   // all 512 writers done; safe reset for next replay
        }
    }
}

extern "C" void kernel_launch(void* const* d_in, const int* in_sizes, int n_in,
                              void* d_out, int out_size) {
    const float* out4d  = (const float*)d_in[0];   // output  [B,C,H,W]
    const int*   mask   = (const int*)  d_in[1];   // mask    [B,K]
    const int*   ind    = (const int*)  d_in[2];   // ind     [B,K]
    const float* target = (const float*)d_in[3];   // target  [B,C,K]
    float* loss = (float*)d_out;

    iou_fused_kernel<<<BKn, 128>>>(out4d, mask, ind, target, loss);
}